// round 14
// baseline (speedup 1.0000x reference)
#include <cuda_runtime.h>
#include <cuda_fp16.h>
#include <stdint.h>

#define NTOK 4096
#define CDIM 64
#define BM   128
#define BN   64
#define NITER (NTOK / BN)       // 64
#define NPROB 18
#define L2E  1.4426950408889634f

// ---------------------------------------------------------------------------
// Device scratch. Contraction-dim storage uses the MMA-fragment permutation
// within each 16-block: stored group 4t..4t+3 = original {2t,2t+1,2t+8,2t+9},
// so an 8-byte load = one (b0,b1) fragment pair.
// K stores hi|lo interleaved per fragment: row = 128 halves,
//   offset(c,sel) = (c>>4)*32 + t(c)*8 + sel*4 + inner(c).
// ---------------------------------------------------------------------------
__device__ __half g_Qhi[3 * 2 * NTOK * CDIM];   // [br][b][n][c'] * log2e, hi
__device__ __half g_Qlo[3 * 2 * NTOK * CDIM];   // residual lo
__device__ __half g_KT [3 * 2 * NTOK * 2 * CDIM]; // [ks][b][j][128] hi|lo interleaved
__device__ __half g_Vh [3 * 2 * CDIM * NTOK];   // [br][b][c][j']

__device__ __host__ __forceinline__ int perm16(int c) {
    int t = (c & 7) >> 1;
    return 4 * t + ((c >> 3) & 1) * 2 + (c & 1);
}

// ---------------------------------------------------------------------------
// Preprocessing
// ---------------------------------------------------------------------------
__global__ void prep_q(const float* __restrict__ q0, const float* __restrict__ q1,
                       const float* __restrict__ q2) {
    int z = blockIdx.y;
    const float* src = (z == 0) ? q0 : (z == 1) ? q1 : q2;
    int i = blockIdx.x * blockDim.x + threadIdx.x;     // [0, 524288)
    float v = src[i] * L2E;
    __half h = __float2half_rn(v);
    int c = i & 63, n = i >> 6;
    int pc = (c & 48) | perm16(c & 15);
    size_t o = (size_t)z * 2 * NTOK * CDIM + (size_t)n * 64 + pc;
    g_Qhi[o] = h;
    g_Qlo[o] = __float2half_rn(v - __half2float(h));
}

__global__ void prep_v(const float* __restrict__ v0, const float* __restrict__ v1,
                       const float* __restrict__ v2) {
    int z = blockIdx.y;
    const float* src = (z == 0) ? v0 : (z == 1) ? v1 : v2;
    int i = blockIdx.x * blockDim.x + threadIdx.x;
    int j = i & 4095, c = i >> 12;
    int pj = (j & ~15) | perm16(j & 15);
    g_Vh[(size_t)z * 2 * CDIM * NTOK + (size_t)c * NTOK + pj] = __float2half_rn(src[i]);
}

// k [b][c][j] -> interleaved kT [j][off(c,sel)]. 32x32 tiles, block (32,8).
__global__ void prep_k(const float* __restrict__ k0, const float* __restrict__ k1,
                       const float* __restrict__ k2) {
    __shared__ float tile[32][33];
    int zb = blockIdx.z;
    int ks = zb >> 1, b = zb & 1;
    const float* src = ((ks == 0) ? k0 : (ks == 1) ? k1 : k2) + (size_t)b * CDIM * NTOK;
    int j0 = blockIdx.x * 32, c0 = blockIdx.y * 32;
    int tx = threadIdx.x, ty = threadIdx.y;
#pragma unroll
    for (int yy = 0; yy < 32; yy += 8)
        tile[ty + yy][tx] = src[(size_t)(c0 + ty + yy) * NTOK + j0 + tx];
    __syncthreads();
    size_t dstbase = ((size_t)ks * 2 + b) * NTOK * 2 * CDIM;
    int c = c0 + tx;
    int base = (c >> 4) * 32 + (((c & 7) >> 1)) * 8 + (((c >> 3) & 1)) * 2 + (c & 1);
#pragma unroll
    for (int yy = 0; yy < 32; yy += 8) {
        int jl = ty + yy;
        float v = tile[tx][jl];
        __half h = __float2half_rn(v);
        size_t o = dstbase + (size_t)(j0 + jl) * 128 + base;
        g_KT[o] = h;                                   // hi at sel=0
        g_KT[o + 4] = __float2half_rn(v - __half2float(h));  // lo at sel=1
    }
}

// ---------------------------------------------------------------------------
// Fast exp2 (FMA pipe). x <= 0 expected; clamped.
// ---------------------------------------------------------------------------
__device__ __forceinline__ float exp2_fast(float x) {
    x = fmaxf(x, -120.0f);
    float r  = __fadd_rn(x, 12582912.0f);
    float k  = __fadd_rn(r, -12582912.0f);
    int   ik = __float_as_int(r) - 0x4B400000;
    float f  = x - k;                              // [-0.5, 0.5]
    float p  = 9.618129107e-3f;
    p = fmaf(p, f, 5.550410866e-2f);
    p = fmaf(p, f, 2.402265069e-1f);
    p = fmaf(p, f, 6.931471806e-1f);
    p = fmaf(p, f, 1.0f);
    return __int_as_float(__float_as_int(p) + (ik << 23));
}

__device__ __forceinline__ uint32_t pack_h2(float a, float b) {
    __half2 h = __floats2half2_rn(a, b);
    return *reinterpret_cast<uint32_t*>(&h);
}
__device__ __forceinline__ void cp_async16(uint32_t saddr, const void* g) {
    asm volatile("cp.async.cg.shared.global [%0], [%1], 16;" :: "r"(saddr), "l"(g));
}

#define MMA16816(D, A, B0, B1)                                                        \
    asm volatile("mma.sync.aligned.m16n8k16.row.col.f32.f16.f16.f32 "                 \
                 "{%0,%1,%2,%3},{%4,%5,%6,%7},{%8,%9},{%0,%1,%2,%3};"                 \
                 : "+f"((D)[0]), "+f"((D)[1]), "+f"((D)[2]), "+f"((D)[3])             \
                 : "r"((A)[0]), "r"((A)[1]), "r"((A)[2]), "r"((A)[3]),                \
                   "r"(B0), "r"(B1))

// ---------------------------------------------------------------------------
// Flash attention + fused conv epilogue.
// grid (32 q-tiles, 18 problems), 256 thr (8 warps x 16 q-rows), 2 CTAs/SM.
// Intra-warp software pipeline per tile:
//   A: GEMM1(h0) -> Sa
//   B: rowmax/m-update(h0) (+acc rescale if max moved)
//   C: GEMM1(h1)->Sb interleaved with exp2/pack(h0)   [tensor || fma]
//   D: rowmax/m-update(h1), l-rescale
//   E: GEMM2(h0) interleaved with exp2/pack(h1)       [tensor || fma]
//   E': acc rescale for h1's max move (after G2(h0) contributions are in)
//   F: GEMM2(h1)
// ---------------------------------------------------------------------------
#define KROWH 160                   // K row stride (halves); conflict-free LDS.128
#define VROWH 80                    // V row stride (halves)
#define KTILE_H (64 * KROWH)        // 10240
#define VTILE_H (64 * VROWH)        // 5120
#define BUF_H  (KTILE_H + VTILE_H)  // 15360 halves per stage
#define SMEM_FLASH (3 * BUF_H * 2)  // 92160 bytes

__global__ void __launch_bounds__(256, 2) flash_kernel(
    const float* __restrict__ w0, const float* __restrict__ w1, const float* __restrict__ w2,
    const float* __restrict__ bi0, const float* __restrict__ bi1, const float* __restrict__ bi2,
    const float* __restrict__ x0, const float* __restrict__ x1, const float* __restrict__ x2,
    float* __restrict__ out)
{
    extern __shared__ __half sm[];
    const int tid = threadIdx.x;
    const int wi = tid >> 5, lane = tid & 31;
    const int g = lane >> 2, t = lane & 3;
    const int pidx = blockIdx.y;
    const int br = pidx / 6, rem = pidx % 6;
    const int ks = rem >> 1, b = rem & 1;
    const int i0 = blockIdx.x * BM + wi * 16;

    const size_t qoff = ((size_t)(br * 2 + b)) * NTOK * CDIM;
    const size_t koff = ((size_t)(ks * 2 + b)) * NTOK * 2 * CDIM;
    const size_t voff = ((size_t)(br * 2 + b)) * CDIM * NTOK;

    const uint32_t smbase = (uint32_t)__cvta_generic_to_shared(sm);

    // Q-hi fragments persist in registers; Q-lo re-loaded per iter via L1 (__ldg)
    uint32_t qh[4][4];
    const __half* Qlo = g_Qlo + qoff;
    {
        const __half* Qh = g_Qhi + qoff;
#pragma unroll
        for (int kc = 0; kc < 4; kc++) {
            int co = kc * 16 + 4 * t;
            uint2 u;
            u = *reinterpret_cast<const uint2*>(Qh + (size_t)(i0 + g) * 64 + co);
            qh[kc][0] = u.x; qh[kc][2] = u.y;
            u = *reinterpret_cast<const uint2*>(Qh + (size_t)(i0 + g + 8) * 64 + co);
            qh[kc][1] = u.x; qh[kc][3] = u.y;
        }
    }
    const uint2* qlp0 = reinterpret_cast<const uint2*>(Qlo + (size_t)(i0 + g) * 64 + 4 * t);
    const uint2* qlp1 = reinterpret_cast<const uint2*>(Qlo + (size_t)(i0 + g + 8) * 64 + 4 * t);

    float m_a = -1e30f, m_b = -1e30f, l_a = 0.0f, l_b = 0.0f;
    float acc[8][4];
#pragma unroll
    for (int n = 0; n < 8; n++)
#pragma unroll
        for (int q = 0; q < 4; q++) acc[n][q] = 0.0f;

    auto issue = [&](int stage, int jt) {
#pragma unroll
        for (int r = 0; r < 4; r++) {
            int idx = tid + 256 * r;
            int row = idx >> 4, c16 = idx & 15;
            int soff = stage * BUF_H + row * KROWH + c16 * 8;
            const __half* gp = g_KT + koff + (size_t)(jt + row) * 128 + c16 * 8;
            cp_async16(smbase + soff * 2, gp);
        }
#pragma unroll
        for (int r = 0; r < 2; r++) {
            int idx = tid + 256 * r;
            int row = idx >> 3, c8 = idx & 7;
            int soff = stage * BUF_H + KTILE_H + row * VROWH + c8 * 8;
            const __half* gp = g_Vh + voff + (size_t)row * NTOK + jt + c8 * 8;
            cp_async16(smbase + soff * 2, gp);
        }
    };

    issue(0, 0);
    asm volatile("cp.async.commit_group;");
    issue(1, BN);
    asm volatile("cp.async.commit_group;");

#pragma unroll 1
    for (int it = 0; it < NITER; it++) {
        if (it < NITER - 1) {
            asm volatile("cp.async.wait_group 1;" ::: "memory");
        } else {
            asm volatile("cp.async.wait_group 0;" ::: "memory");
        }
        __syncthreads();
        if (it < NITER - 2) {
            int nx = it + 2;
            issue(nx % 3, nx * BN);
            asm volatile("cp.async.commit_group;");
        }

        const __half* sK = sm + (it % 3) * BUF_H;
        const __half* sV = sK + KTILE_H;

        float Sa[4][4], Sb[4][4];
        uint32_t paA[8], paB[8];

        // ---- A: GEMM1(h0) -> Sa (3 f32-acc MMAs per fragment) ----
#pragma unroll
        for (int n = 0; n < 4; n++) Sa[n][0] = Sa[n][1] = Sa[n][2] = Sa[n][3] = 0.0f;
#pragma unroll
        for (int kc = 0; kc < 4; kc++) {
            uint32_t ql[4];
            uint2 u = __ldg(qlp0 + kc * 2); ql[0] = u.x; ql[2] = u.y;
            u = __ldg(qlp1 + kc * 2);       ql[1] = u.x; ql[3] = u.y;
#pragma unroll
            for (int n2 = 0; n2 < 4; n2++) {
                const __half* kp = sK + (8 * n2 + g) * KROWH + kc * 32 + t * 8;
                uint4 kb = *reinterpret_cast<const uint4*>(kp);
                MMA16816(Sa[n2], qh[kc], kb.x, kb.y);
                MMA16816(Sa[n2], ql,     kb.x, kb.y);
                MMA16816(Sa[n2], qh[kc], kb.z, kb.w);
            }
        }

        // ---- B: rowmax + m-update for h0 (+acc rescale if moved) ----
        {
            float ra = fmaxf(fmaxf(Sa[0][0], Sa[0][1]), fmaxf(Sa[1][0], Sa[1][1]));
            float rb = fmaxf(fmaxf(Sa[0][2], Sa[0][3]), fmaxf(Sa[1][2], Sa[1][3]));
            ra = fmaxf(ra, fmaxf(fmaxf(Sa[2][0], Sa[2][1]), fmaxf(Sa[3][0], Sa[3][1])));
            rb = fmaxf(rb, fmaxf(fmaxf(Sa[2][2], Sa[2][3]), fmaxf(Sa[3][2], Sa[3][3])));
            ra = fmaxf(ra, __shfl_xor_sync(0xffffffffu, ra, 1));
            ra = fmaxf(ra, __shfl_xor_sync(0xffffffffu, ra, 2));
            rb = fmaxf(rb, __shfl_xor_sync(0xffffffffu, rb, 1));
            rb = fmaxf(rb, __shfl_xor_sync(0xffffffffu, rb, 2));
            float mna = fmaxf(m_a, ra), mnb = fmaxf(m_b, rb);
            if (!__all_sync(0xffffffffu, (mna == m_a) & (mnb == m_b))) {
                float sca = exp2_fast(m_a - mna), scb = exp2_fast(m_b - mnb);
                m_a = mna; m_b = mnb;
                l_a *= sca; l_b *= scb;
#pragma unroll
                for (int nc = 0; nc < 8; nc++) {
                    acc[nc][0] *= sca; acc[nc][1] *= sca;
                    acc[nc][2] *= scb; acc[nc][3] *= scb;
                }
            }
        }

        // ---- C: GEMM1(h1)->Sb interleaved with exp2/pack of Sa ----
#pragma unroll
        for (int n = 0; n < 4; n++) Sb[n][0] = Sb[n][1] = Sb[n][2] = Sb[n][3] = 0.0f;
#pragma unroll
        for (int kc = 0; kc < 4; kc++) {
            uint32_t ql[4];
            uint2 u = __ldg(qlp0 + kc * 2); ql[0] = u.x; ql[2] = u.y;
            u = __ldg(qlp1 + kc * 2);       ql[1] = u.x; ql[3] = u.y;
#pragma unroll
            for (int n2 = 0; n2 < 4; n2++) {
                const __half* kp = sK + (8 * (4 + n2) + g) * KROWH + kc * 32 + t * 8;
                uint4 kb = *reinterpret_cast<const uint4*>(kp);
                MMA16816(Sb[n2], qh[kc], kb.x, kb.y);
                MMA16816(Sb[n2], ql,     kb.x, kb.y);
                MMA16816(Sb[n2], qh[kc], kb.z, kb.w);
            }
            // softmax slice for Sa[n2=kc] (independent of the MMAs above)
            {
                int n2 = kc;
                float e0 = exp2_fast(Sa[n2][0] - m_a);
                float e1 = exp2_fast(Sa[n2][1] - m_a);
                float e2 = exp2_fast(Sa[n2][2] - m_b);
                float e3 = exp2_fast(Sa[n2][3] - m_b);
                l_a += e0 + e1; l_b += e2 + e3;
                paA[4 * (n2 >> 1) + 2 * (n2 & 1) + 0] = pack_h2(e0, e1);
                paA[4 * (n2 >> 1) + 2 * (n2 & 1) + 1] = pack_h2(e2, e3);
            }
        }

        // ---- D: rowmax + m-update for h1 (l-rescale now; acc-rescale after E) ----
        float sca = 1.0f, scb = 1.0f;
        bool need_rs = false;
        {
            float ra = fmaxf(fmaxf(Sb[0][0], Sb[0][1]), fmaxf(Sb[1][0], Sb[1][1]));
            float rb = fmaxf(fmaxf(Sb[0][2], Sb[0][3]), fmaxf(Sb[1][2], Sb[1][3]));
            ra = fmaxf(ra, fmaxf(fmaxf(Sb[2][0], Sb[2][1]), fmaxf(Sb[3][0], Sb[3][1])));
            rb = fmaxf(rb, fmaxf(fmaxf(Sb[2][2], Sb[2][3]), fmaxf(Sb[3][2], Sb[3][3])));
            ra = fmaxf(ra, __shfl_xor_sync(0xffffffffu, ra, 1));
            ra = fmaxf(ra, __shfl_xor_sync(0xffffffffu, ra, 2));
            rb = fmaxf(rb, __shfl_xor_sync(0xffffffffu, rb, 1));
            rb = fmaxf(rb, __shfl_xor_sync(0xffffffffu, rb, 2));
            float mna = fmaxf(m_a, ra), mnb = fmaxf(m_b, rb);
            if (!__all_sync(0xffffffffu, (mna == m_a) & (mnb == m_b))) {
                need_rs = true;
                sca = exp2_fast(m_a - mna); scb = exp2_fast(m_b - mnb);
                m_a = mna; m_b = mnb;
                l_a *= sca; l_b *= scb;
            }
        }

        // ---- E: GEMM2(h0) interleaved with exp2/pack of Sb ----
#pragma unroll
        for (int kj2 = 0; kj2 < 2; kj2++) {
            int kj = kj2;                  // h0 columns
#pragma unroll
            for (int nc = 0; nc < 8; nc++) {
                const __half* vp = sV + (8 * nc + g) * VROWH + kj * 16 + 4 * t;
                uint2 vv = *reinterpret_cast<const uint2*>(vp);
                MMA16816(acc[nc], paA + 4 * kj2, vv.x, vv.y);
            }
            // softmax slices for Sb n2 = 2*kj2, 2*kj2+1 (independent)
#pragma unroll
            for (int q2 = 0; q2 < 2; q2++) {
                int n2 = 2 * kj2 + q2;
                float e0 = exp2_fast(Sb[n2][0] - m_a);
                float e1 = exp2_fast(Sb[n2][1] - m_a);
                float e2 = exp2_fast(Sb[n2][2] - m_b);
                float e3 = exp2_fast(Sb[n2][3] - m_b);
                l_a += e0 + e1; l_b += e2 + e3;
                paB[4 * (n2 >> 1) + 2 * (n2 & 1) + 0] = pack_h2(e0, e1);
                paB[4 * (n2 >> 1) + 2 * (n2 & 1) + 1] = pack_h2(e2, e3);
            }
        }

        // acc rescale for h1's max move (must cover h0's contributions, now in)
        if (need_rs) {
#pragma unroll
            for (int nc = 0; nc < 8; nc++) {
                acc[nc][0] *= sca; acc[nc][1] *= sca;
                acc[nc][2] *= scb; acc[nc][3] *= scb;
            }
        }

        // ---- F: GEMM2(h1) ----
#pragma unroll
        for (int kj2 = 0; kj2 < 2; kj2++) {
            int kj = 2 + kj2;              // h1 columns
#pragma unroll
            for (int nc = 0; nc < 8; nc++) {
                const __half* vp = sV + (8 * nc + g) * VROWH + kj * 16 + 4 * t;
                uint2 vv = *reinterpret_cast<const uint2*>(vp);
                MMA16816(acc[nc], paB + 4 * kj2, vv.x, vv.y);
            }
        }
    }

    // Row denominators: sum partials across the 4 t-lanes of each group
    l_a += __shfl_xor_sync(0xffffffffu, l_a, 1);
    l_a += __shfl_xor_sync(0xffffffffu, l_a, 2);
    l_b += __shfl_xor_sync(0xffffffffu, l_b, 1);
    l_b += __shfl_xor_sync(0xffffffffu, l_b, 2);
    float ia = 1.0f / l_a, ib = 1.0f / l_b;

    // ---------------- Fused conv epilogue ----------------
    const float* w  = (br == 0) ? w0  : (br == 1) ? w1  : w2;
    const float* bi = (br == 0) ? bi0 : (br == 1) ? bi1 : bi2;
    const float* x  = (br == 0) ? x0  : (br == 1) ? x1  : x2;

    __syncthreads();   // all reads of pipeline smem done; reuse stage 0
    __half* ws = sm;                       // [64][80] halves, c permuted
    float*  bsf = (float*)(sm + 64 * VROWH);
#pragma unroll
    for (int r = 0; r < 16; r++) {
        int idx = tid + 256 * r;           // 4096 weights
        int oc = idx >> 6, c = idx & 63;
        ws[oc * VROWH + (c & 48) + perm16(c & 15)] = __float2half_rn(w[idx]);
    }
    if (tid < 64) bsf[tid] = bi[tid];
    __syncthreads();

    // A fragments = normalized O (same repacking pattern as P)
    uint32_t oa[4][4];
#pragma unroll
    for (int kc = 0; kc < 4; kc++) {
        oa[kc][0] = pack_h2(acc[2 * kc][0] * ia,     acc[2 * kc][1] * ia);
        oa[kc][1] = pack_h2(acc[2 * kc][2] * ib,     acc[2 * kc][3] * ib);
        oa[kc][2] = pack_h2(acc[2 * kc + 1][0] * ia, acc[2 * kc + 1][1] * ia);
        oa[kc][3] = pack_h2(acc[2 * kc + 1][2] * ib, acc[2 * kc + 1][3] * ib);
    }

    float D[8][4];
#pragma unroll
    for (int n = 0; n < 8; n++) D[n][0] = D[n][1] = D[n][2] = D[n][3] = 0.0f;
#pragma unroll
    for (int kc = 0; kc < 4; kc++) {
#pragma unroll
        for (int nw = 0; nw < 8; nw++) {
            const __half* wp = ws + (8 * nw + g) * VROWH + kc * 16 + 4 * t;
            uint2 wb = *reinterpret_cast<const uint2*>(wp);
            MMA16816(D[nw], oa[kc], wb.x, wb.y);
        }
    }

    // out[br][b][ks*64+oc][i] = D + bias[oc] + x[b][oc][i]
    float* ob = out + (size_t)br * (2 * 192 * NTOK) + (size_t)b * (192 * NTOK)
                    + (size_t)ks * (64 * NTOK);
    const float* xb = x + (size_t)b * CDIM * NTOK;
#pragma unroll
    for (int nw = 0; nw < 8; nw++) {
        int oc = 8 * nw + 2 * t;
        float bs0 = bsf[oc], bs1 = bsf[oc + 1];
        size_t o00 = (size_t)oc * NTOK + i0 + g;
        ob[o00]            = D[nw][0] + bs0 + xb[o00];
        ob[o00 + NTOK]     = D[nw][1] + bs1 + xb[o00 + NTOK];
        size_t o10 = o00 + 8;
        ob[o10]            = D[nw][2] + bs0 + xb[o10];
        ob[o10 + NTOK]     = D[nw][3] + bs1 + xb[o10 + NTOK];
    }
}

// ---------------------------------------------------------------------------
// Launch. Inputs in setup_inputs() dict-insertion order.
// ---------------------------------------------------------------------------
extern "C" void kernel_launch(void* const* d_in, const int* in_sizes, int n_in,
                              void* d_out, int out_size) {
    const float* poi_q   = (const float*)d_in[0];
    const float* poi_k   = (const float*)d_in[1];
    const float* poi_v   = (const float*)d_in[2];
    const float* x_poi   = (const float*)d_in[3];
    const float* point_q = (const float*)d_in[4];
    const float* point_k = (const float*)d_in[5];
    const float* point_v = (const float*)d_in[6];
    const float* x_point = (const float*)d_in[7];
    const float* pop_q   = (const float*)d_in[8];
    const float* pop_k   = (const float*)d_in[9];
    const float* pop_v   = (const float*)d_in[10];
    const float* x_pop   = (const float*)d_in[11];
    const float* w_poi   = (const float*)d_in[12];
    const float* b_poi   = (const float*)d_in[13];
    const float* w_point = (const float*)d_in[14];
    const float* b_point = (const float*)d_in[15];
    const float* w_pop   = (const float*)d_in[16];
    const float* b_pop   = (const float*)d_in[17];
    float* out = (float*)d_out;

    cudaFuncSetAttribute(flash_kernel, cudaFuncAttributeMaxDynamicSharedMemorySize,
                         SMEM_FLASH);

    prep_q<<<dim3(2048, 3), 256>>>(poi_q, point_q, pop_q);
    prep_v<<<dim3(2048, 3), 256>>>(poi_v, point_v, pop_v);
    prep_k<<<dim3(128, 2, 6), dim3(32, 8)>>>(poi_k, point_k, pop_k);
    flash_kernel<<<dim3(32, 18), 256, SMEM_FLASH>>>(
        w_poi, w_point, w_pop, b_poi, b_point, b_pop,
        x_poi, x_point, x_pop, out);
}

// round 15
// speedup vs baseline: 1.0267x; 1.0267x over previous
#include <cuda_runtime.h>
#include <cuda_fp16.h>
#include <stdint.h>

#define NTOK 4096
#define CDIM 64
#define BM   128
#define BN   64
#define NITER (NTOK / BN)       // 64
#define NPROB 18
#define L2E  1.4426950408889634f

// ---------------------------------------------------------------------------
// Device scratch. Contraction-dim storage uses the MMA-fragment permutation
// within each 16-block: stored group 4t..4t+3 = original {2t,2t+1,2t+8,2t+9},
// so an 8-byte load = one (b0,b1) fragment pair.
// K stores hi|lo interleaved per fragment: row = 128 halves.
// ---------------------------------------------------------------------------
__device__ __half g_Qhi[3 * 2 * NTOK * CDIM];   // [br][b][n][c'] * log2e, hi
__device__ __half g_Qlo[3 * 2 * NTOK * CDIM];   // residual lo
__device__ __half g_KT [3 * 2 * NTOK * 2 * CDIM]; // [ks][b][j][128] hi|lo interleaved
__device__ __half g_Vh [3 * 2 * CDIM * NTOK];   // [br][b][c][j']

__device__ __host__ __forceinline__ int perm16(int c) {
    int t = (c & 7) >> 1;
    return 4 * t + ((c >> 3) & 1) * 2 + (c & 1);
}

// ---------------------------------------------------------------------------
// Preprocessing
// ---------------------------------------------------------------------------
__global__ void prep_q(const float* __restrict__ q0, const float* __restrict__ q1,
                       const float* __restrict__ q2) {
    int z = blockIdx.y;
    const float* src = (z == 0) ? q0 : (z == 1) ? q1 : q2;
    int i = blockIdx.x * blockDim.x + threadIdx.x;     // [0, 524288)
    float v = src[i] * L2E;
    __half h = __float2half_rn(v);
    int c = i & 63, n = i >> 6;
    int pc = (c & 48) | perm16(c & 15);
    size_t o = (size_t)z * 2 * NTOK * CDIM + (size_t)n * 64 + pc;
    g_Qhi[o] = h;
    g_Qlo[o] = __float2half_rn(v - __half2float(h));
}

__global__ void prep_v(const float* __restrict__ v0, const float* __restrict__ v1,
                       const float* __restrict__ v2) {
    int z = blockIdx.y;
    const float* src = (z == 0) ? v0 : (z == 1) ? v1 : v2;
    int i = blockIdx.x * blockDim.x + threadIdx.x;
    int j = i & 4095, c = i >> 12;
    int pj = (j & ~15) | perm16(j & 15);
    g_Vh[(size_t)z * 2 * CDIM * NTOK + (size_t)c * NTOK + pj] = __float2half_rn(src[i]);
}

// k [b][c][j] -> interleaved kT [j][off(c,sel)]. 32x32 tiles, block (32,8).
__global__ void prep_k(const float* __restrict__ k0, const float* __restrict__ k1,
                       const float* __restrict__ k2) {
    __shared__ float tile[32][33];
    int zb = blockIdx.z;
    int ks = zb >> 1, b = zb & 1;
    const float* src = ((ks == 0) ? k0 : (ks == 1) ? k1 : k2) + (size_t)b * CDIM * NTOK;
    int j0 = blockIdx.x * 32, c0 = blockIdx.y * 32;
    int tx = threadIdx.x, ty = threadIdx.y;
#pragma unroll
    for (int yy = 0; yy < 32; yy += 8)
        tile[ty + yy][tx] = src[(size_t)(c0 + ty + yy) * NTOK + j0 + tx];
    __syncthreads();
    size_t dstbase = ((size_t)ks * 2 + b) * NTOK * 2 * CDIM;
    int c = c0 + tx;
    int base = (c >> 4) * 32 + (((c & 7) >> 1)) * 8 + (((c >> 3) & 1)) * 2 + (c & 1);
#pragma unroll
    for (int yy = 0; yy < 32; yy += 8) {
        int jl = ty + yy;
        float v = tile[tx][jl];
        __half h = __float2half_rn(v);
        size_t o = dstbase + (size_t)(j0 + jl) * 128 + base;
        g_KT[o] = h;                                   // hi at sel=0
        g_KT[o + 4] = __float2half_rn(v - __half2float(h));  // lo at sel=1
    }
}

// ---------------------------------------------------------------------------
// Fast exp2 (FMA pipe). x <= 0 expected; clamped.
// ---------------------------------------------------------------------------
__device__ __forceinline__ float exp2_fast(float x) {
    x = fmaxf(x, -120.0f);
    float r  = __fadd_rn(x, 12582912.0f);
    float k  = __fadd_rn(r, -12582912.0f);
    int   ik = __float_as_int(r) - 0x4B400000;
    float f  = x - k;                              // [-0.5, 0.5]
    float p  = 9.618129107e-3f;
    p = fmaf(p, f, 5.550410866e-2f);
    p = fmaf(p, f, 2.402265069e-1f);
    p = fmaf(p, f, 6.931471806e-1f);
    p = fmaf(p, f, 1.0f);
    return __int_as_float(__float_as_int(p) + (ik << 23));
}

__device__ __forceinline__ uint32_t pack_h2(float a, float b) {
    __half2 h = __floats2half2_rn(a, b);
    return *reinterpret_cast<uint32_t*>(&h);
}
__device__ __forceinline__ void cp_async16(uint32_t saddr, const void* g) {
    asm volatile("cp.async.cg.shared.global [%0], [%1], 16;" :: "r"(saddr), "l"(g));
}
// Arrive-on: one async arrival per executing thread once its prior cp.asyncs land.
__device__ __forceinline__ void cp_arrive(uint32_t mbar) {
    asm volatile("cp.async.mbarrier.arrive.noinc.shared.b64 [%0];" :: "r"(mbar) : "memory");
}
__device__ __forceinline__ void mb_init(uint32_t mbar, uint32_t cnt) {
    asm volatile("mbarrier.init.shared.b64 [%0], %1;" :: "r"(mbar), "r"(cnt) : "memory");
}
__device__ __forceinline__ void mb_arrive(uint32_t mbar) {
    asm volatile("mbarrier.arrive.release.cta.shared.b64 _, [%0];" :: "r"(mbar) : "memory");
}
__device__ __forceinline__ void mb_wait(uint32_t mbar, uint32_t par) {
    asm volatile("{\n\t.reg .pred P1;\n\t"
        "W_%=:\n\t"
        "mbarrier.try_wait.parity.acquire.cta.shared::cta.b64 P1, [%0], %1, 0x989680;\n\t"
        "@P1 bra.uni D_%=;\n\t"
        "bra.uni W_%=;\n\t"
        "D_%=:\n\t}" :: "r"(mbar), "r"(par) : "memory");
}

#define MMA16816(D, A, B0, B1)                                                        \
    asm volatile("mma.sync.aligned.m16n8k16.row.col.f32.f16.f16.f32 "                 \
                 "{%0,%1,%2,%3},{%4,%5,%6,%7},{%8,%9},{%0,%1,%2,%3};"                 \
                 : "+f"((D)[0]), "+f"((D)[1]), "+f"((D)[2]), "+f"((D)[3])             \
                 : "r"((A)[0]), "r"((A)[1]), "r"((A)[2]), "r"((A)[3]),                \
                   "r"(B0), "r"(B1))

#define MMA16816H(C, A, B0, B1)                                                       \
    asm volatile("mma.sync.aligned.m16n8k16.row.col.f16.f16.f16.f16 "                 \
                 "{%0,%1},{%2,%3,%4,%5},{%6,%7},{%0,%1};"                             \
                 : "+r"((C)[0]), "+r"((C)[1])                                         \
                 : "r"((A)[0]), "r"((A)[1]), "r"((A)[2]), "r"((A)[3]),                \
                   "r"(B0), "r"(B1))

// ---------------------------------------------------------------------------
// Flash attention + fused conv epilogue.
// grid (32 q-tiles, 18 problems), 256 thr (8 warps x 16 q-rows), 2 CTAs/SM.
// NO mainloop __syncthreads: 3-stage ring with mbarriers lets warps self-skew
// up to ~1 iteration so softmax (fma pipe) overlaps other warps' MMAs.
//   full[b] (count 256): cp.async arrive-on per thread (data landed)
//   free[b] (count 256): per-lane release after consuming (orders own reads)
// ---------------------------------------------------------------------------
#define KROWH 160                   // K row stride (halves); conflict-free LDS.128
#define VROWH 80                    // V row stride (halves)
#define KTILE_H (64 * KROWH)        // 10240
#define VTILE_H (64 * VROWH)        // 5120
#define BUF_H  (KTILE_H + VTILE_H)  // 15360 halves per stage
#define HDR_H  64                   // 128-byte header for mbarriers
#define SMEM_FLASH ((HDR_H + 3 * BUF_H) * 2)   // 92288 bytes

__global__ void __launch_bounds__(256, 2) flash_kernel(
    const float* __restrict__ w0, const float* __restrict__ w1, const float* __restrict__ w2,
    const float* __restrict__ bi0, const float* __restrict__ bi1, const float* __restrict__ bi2,
    const float* __restrict__ x0, const float* __restrict__ x1, const float* __restrict__ x2,
    float* __restrict__ out)
{
    extern __shared__ __half sm[];
    __half* smb = sm + HDR_H;              // staging buffers
    const int tid = threadIdx.x;
    const int wi = tid >> 5, lane = tid & 31;
    const int g = lane >> 2, t = lane & 3;
    const int pidx = blockIdx.y;
    const int br = pidx / 6, rem = pidx % 6;
    const int ks = rem >> 1, b = rem & 1;
    const int i0 = blockIdx.x * BM + wi * 16;

    const size_t qoff = ((size_t)(br * 2 + b)) * NTOK * CDIM;
    const size_t koff = ((size_t)(ks * 2 + b)) * NTOK * 2 * CDIM;
    const size_t voff = ((size_t)(br * 2 + b)) * CDIM * NTOK;

    const uint32_t mbase = (uint32_t)__cvta_generic_to_shared(sm);
    const uint32_t smbase = mbase + HDR_H * 2;
    // mbarrier slots: full[b] at +0,8,16 ; free[b] at +24,32,40
    if (tid == 0) {
#pragma unroll
        for (int s = 0; s < 3; s++) {
            mb_init(mbase + s * 8, 256);        // full
            mb_init(mbase + 24 + s * 8, 256);   // free
        }
    }
    __syncthreads();

    // Q fragments (persist)
    uint32_t qh[4][4], ql[4][4];
    {
        const __half* Qh = g_Qhi + qoff;
        const __half* Ql = g_Qlo + qoff;
#pragma unroll
        for (int kc = 0; kc < 4; kc++) {
            int co = kc * 16 + 4 * t;
            uint2 u;
            u = *reinterpret_cast<const uint2*>(Qh + (size_t)(i0 + g) * 64 + co);
            qh[kc][0] = u.x; qh[kc][2] = u.y;
            u = *reinterpret_cast<const uint2*>(Qh + (size_t)(i0 + g + 8) * 64 + co);
            qh[kc][1] = u.x; qh[kc][3] = u.y;
            u = *reinterpret_cast<const uint2*>(Ql + (size_t)(i0 + g) * 64 + co);
            ql[kc][0] = u.x; ql[kc][2] = u.y;
            u = *reinterpret_cast<const uint2*>(Ql + (size_t)(i0 + g + 8) * 64 + co);
            ql[kc][1] = u.x; ql[kc][3] = u.y;
        }
    }

    float m_a = -1e30f, m_b = -1e30f, l_a = 0.0f, l_b = 0.0f;
    float acc[8][4];
#pragma unroll
    for (int n = 0; n < 8; n++)
#pragma unroll
        for (int q = 0; q < 4; q++) acc[n][q] = 0.0f;

    auto produce = [&](int stage, int jt) {
#pragma unroll
        for (int r = 0; r < 4; r++) {
            int idx = tid + 256 * r;
            int row = idx >> 4, c16 = idx & 15;
            int soff = stage * BUF_H + row * KROWH + c16 * 8;
            const __half* gp = g_KT + koff + (size_t)(jt + row) * 128 + c16 * 8;
            cp_async16(smbase + soff * 2, gp);
        }
#pragma unroll
        for (int r = 0; r < 2; r++) {
            int idx = tid + 256 * r;
            int row = idx >> 3, c8 = idx & 7;
            int soff = stage * BUF_H + KTILE_H + row * VROWH + c8 * 8;
            const __half* gp = g_Vh + voff + (size_t)row * NTOK + jt + c8 * 8;
            cp_async16(smbase + soff * 2, gp);
        }
    };

    // prologue: fill stages 0 and 1 (stage 2 produced at s=0)
    produce(0, 0);      cp_arrive(mbase + 0 * 8);
    produce(1, BN);     cp_arrive(mbase + 1 * 8);

#pragma unroll 1
    for (int it = 0; it < NITER; it++) {
        // produce stage it+2 into buffer (it+2)%3
        if (it + 2 < NITER) {
            int s2 = it + 2, b2 = s2 % 3;
            if (s2 >= 3) mb_wait(mbase + 24 + b2 * 8, ((s2 / 3) - 1) & 1);
            produce(b2, s2 * BN);
            cp_arrive(mbase + b2 * 8);
        }
        const int bb = it % 3;
        mb_wait(mbase + bb * 8, (it / 3) & 1);

        const __half* sK = smb + bb * BUF_H;
        const __half* sV = sK + KTILE_H;

#pragma unroll
        for (int h = 0; h < 2; h++) {
            const int half = h ^ (wi & 1);
            float S[4][4];
            uint32_t corr[4][2];
#pragma unroll
            for (int n = 0; n < 4; n++) {
                S[n][0] = S[n][1] = S[n][2] = S[n][3] = 0.0f;
                corr[n][0] = corr[n][1] = 0u;
            }

            // GEMM1: main (f32 acc) + corrections (f16 acc)
#pragma unroll
            for (int kc = 0; kc < 4; kc++) {
#pragma unroll
                for (int n2 = 0; n2 < 4; n2++) {
                    int nc = 4 * half + n2;
                    const __half* kp = sK + (8 * nc + g) * KROWH + kc * 32 + t * 8;
                    uint4 kb = *reinterpret_cast<const uint4*>(kp);
                    MMA16816(S[n2], qh[kc], kb.x, kb.y);
                    MMA16816H(corr[n2], ql[kc], kb.x, kb.y);
                    MMA16816H(corr[n2], qh[kc], kb.z, kb.w);
                }
            }
#pragma unroll
            for (int n2 = 0; n2 < 4; n2++) {
                float2 lo = __half22float2(*reinterpret_cast<__half2*>(&corr[n2][0]));
                float2 hi = __half22float2(*reinterpret_cast<__half2*>(&corr[n2][1]));
                S[n2][0] += lo.x; S[n2][1] += lo.y;
                S[n2][2] += hi.x; S[n2][3] += hi.y;
            }

            // Online softmax over 32 cols (base 2)
            float rmax_a = fmaxf(fmaxf(S[0][0], S[0][1]), fmaxf(S[1][0], S[1][1]));
            float rmax_b = fmaxf(fmaxf(S[0][2], S[0][3]), fmaxf(S[1][2], S[1][3]));
            rmax_a = fmaxf(rmax_a, fmaxf(fmaxf(S[2][0], S[2][1]), fmaxf(S[3][0], S[3][1])));
            rmax_b = fmaxf(rmax_b, fmaxf(fmaxf(S[2][2], S[2][3]), fmaxf(S[3][2], S[3][3])));
            rmax_a = fmaxf(rmax_a, __shfl_xor_sync(0xffffffffu, rmax_a, 1));
            rmax_a = fmaxf(rmax_a, __shfl_xor_sync(0xffffffffu, rmax_a, 2));
            rmax_b = fmaxf(rmax_b, __shfl_xor_sync(0xffffffffu, rmax_b, 1));
            rmax_b = fmaxf(rmax_b, __shfl_xor_sync(0xffffffffu, rmax_b, 2));

            float mna = fmaxf(m_a, rmax_a), mnb = fmaxf(m_b, rmax_b);
            if (!__all_sync(0xffffffffu, (mna == m_a) & (mnb == m_b))) {
                float sca = exp2_fast(m_a - mna), scb = exp2_fast(m_b - mnb);
                m_a = mna; m_b = mnb;
                l_a *= sca; l_b *= scb;
#pragma unroll
                for (int nc = 0; nc < 8; nc++) {
                    acc[nc][0] *= sca; acc[nc][1] *= sca;
                    acc[nc][2] *= scb; acc[nc][3] *= scb;
                }
            }
#pragma unroll
            for (int n2 = 0; n2 < 4; n2++) {
                S[n2][0] = exp2_fast(S[n2][0] - m_a);
                S[n2][1] = exp2_fast(S[n2][1] - m_a);
                S[n2][2] = exp2_fast(S[n2][2] - m_b);
                S[n2][3] = exp2_fast(S[n2][3] - m_b);
                l_a += S[n2][0] + S[n2][1];
                l_b += S[n2][2] + S[n2][3];
            }

            // GEMM2: acc += P * V^T
#pragma unroll
            for (int kj2 = 0; kj2 < 2; kj2++) {
                int kj = 2 * half + kj2;
                uint32_t pa[4];
                pa[0] = pack_h2(S[2 * kj2][0],     S[2 * kj2][1]);
                pa[1] = pack_h2(S[2 * kj2][2],     S[2 * kj2][3]);
                pa[2] = pack_h2(S[2 * kj2 + 1][0], S[2 * kj2 + 1][1]);
                pa[3] = pack_h2(S[2 * kj2 + 1][2], S[2 * kj2 + 1][3]);
#pragma unroll
                for (int nc = 0; nc < 8; nc++) {
                    const __half* vp = sV + (8 * nc + g) * VROWH + kj * 16 + 4 * t;
                    uint2 vv = *reinterpret_cast<const uint2*>(vp);
                    MMA16816(acc[nc], pa, vv.x, vv.y);
                }
            }
        }

        // release this stage (every lane: release-arrive orders its own reads)
        mb_arrive(mbase + 24 + bb * 8);
    }

    // Row denominators: sum partials across the 4 t-lanes of each group
    l_a += __shfl_xor_sync(0xffffffffu, l_a, 1);
    l_a += __shfl_xor_sync(0xffffffffu, l_a, 2);
    l_b += __shfl_xor_sync(0xffffffffu, l_b, 1);
    l_b += __shfl_xor_sync(0xffffffffu, l_b, 2);
    float ia = 1.0f / l_a, ib = 1.0f / l_b;

    // ---------------- Fused conv epilogue ----------------
    const float* w  = (br == 0) ? w0  : (br == 1) ? w1  : w2;
    const float* bi = (br == 0) ? bi0 : (br == 1) ? bi1 : bi2;
    const float* x  = (br == 0) ? x0  : (br == 1) ? x1  : x2;

    __syncthreads();   // all warps done with staging buffers; reuse them
    __half* ws = smb;                      // [64][80] halves, c permuted
    float*  bsf = (float*)(smb + 64 * VROWH);
#pragma unroll
    for (int r = 0; r < 16; r++) {
        int idx = tid + 256 * r;           // 4096 weights
        int oc = idx >> 6, c = idx & 63;
        ws[oc * VROWH + (c & 48) + perm16(c & 15)] = __float2half_rn(w[idx]);
    }
    if (tid < 64) bsf[tid] = bi[tid];
    __syncthreads();

    uint32_t oa[4][4];
#pragma unroll
    for (int kc = 0; kc < 4; kc++) {
        oa[kc][0] = pack_h2(acc[2 * kc][0] * ia,     acc[2 * kc][1] * ia);
        oa[kc][1] = pack_h2(acc[2 * kc][2] * ib,     acc[2 * kc][3] * ib);
        oa[kc][2] = pack_h2(acc[2 * kc + 1][0] * ia, acc[2 * kc + 1][1] * ia);
        oa[kc][3] = pack_h2(acc[2 * kc + 1][2] * ib, acc[2 * kc + 1][3] * ib);
    }

    float D[8][4];
#pragma unroll
    for (int n = 0; n < 8; n++) D[n][0] = D[n][1] = D[n][2] = D[n][3] = 0.0f;
#pragma unroll
    for (int kc = 0; kc < 4; kc++) {
#pragma unroll
        for (int nw = 0; nw < 8; nw++) {
            const __half* wp = ws + (8 * nw + g) * VROWH + kc * 16 + 4 * t;
            uint2 wb = *reinterpret_cast<const uint2*>(wp);
            MMA16816(D[nw], oa[kc], wb.x, wb.y);
        }
    }

    // out[br][b][ks*64+oc][i] = D + bias[oc] + x[b][oc][i]
    float* ob = out + (size_t)br * (2 * 192 * NTOK) + (size_t)b * (192 * NTOK)
                    + (size_t)ks * (64 * NTOK);
    const float* xb = x + (size_t)b * CDIM * NTOK;
#pragma unroll
    for (int nw = 0; nw < 8; nw++) {
        int oc = 8 * nw + 2 * t;
        float bs0 = bsf[oc], bs1 = bsf[oc + 1];
        size_t o00 = (size_t)oc * NTOK + i0 + g;
        ob[o00]            = D[nw][0] + bs0 + xb[o00];
        ob[o00 + NTOK]     = D[nw][1] + bs1 + xb[o00 + NTOK];
        size_t o10 = o00 + 8;
        ob[o10]            = D[nw][2] + bs0 + xb[o10];
        ob[o10 + NTOK]     = D[nw][3] + bs1 + xb[o10 + NTOK];
    }
}

// ---------------------------------------------------------------------------
// Launch. Inputs in setup_inputs() dict-insertion order.
// ---------------------------------------------------------------------------
extern "C" void kernel_launch(void* const* d_in, const int* in_sizes, int n_in,
                              void* d_out, int out_size) {
    const float* poi_q   = (const float*)d_in[0];
    const float* poi_k   = (const float*)d_in[1];
    const float* poi_v   = (const float*)d_in[2];
    const float* x_poi   = (const float*)d_in[3];
    const float* point_q = (const float*)d_in[4];
    const float* point_k = (const float*)d_in[5];
    const float* point_v = (const float*)d_in[6];
    const float* x_point = (const float*)d_in[7];
    const float* pop_q   = (const float*)d_in[8];
    const float* pop_k   = (const float*)d_in[9];
    const float* pop_v   = (const float*)d_in[10];
    const float* x_pop   = (const float*)d_in[11];
    const float* w_poi   = (const float*)d_in[12];
    const float* b_poi   = (const float*)d_in[13];
    const float* w_point = (const float*)d_in[14];
    const float* b_point = (const float*)d_in[15];
    const float* w_pop   = (const float*)d_in[16];
    const float* b_pop   = (const float*)d_in[17];
    float* out = (float*)d_out;

    cudaFuncSetAttribute(flash_kernel, cudaFuncAttributeMaxDynamicSharedMemorySize,
                         SMEM_FLASH);

    prep_q<<<dim3(2048, 3), 256>>>(poi_q, point_q, pop_q);
    prep_v<<<dim3(2048, 3), 256>>>(poi_v, point_v, pop_v);
    prep_k<<<dim3(128, 2, 6), dim3(32, 8)>>>(poi_k, point_k, pop_k);
    flash_kernel<<<dim3(32, 18), 256, SMEM_FLASH>>>(
        w_poi, w_point, w_pop, b_poi, b_point, b_pop,
        x_poi, x_point, x_pop, out);
}

// round 16
// speedup vs baseline: 1.2759x; 1.2428x over previous
#include <cuda_runtime.h>
#include <cuda_fp16.h>
#include <stdint.h>

#define NTOK 4096
#define CDIM 64
#define BM   128
#define BN   64
#define NITER (NTOK / BN)       // 64
#define NPROB 18
#define L2E  1.4426950408889634f

// ---------------------------------------------------------------------------
// Device scratch. Contraction-dim storage uses the MMA-fragment permutation
// within each 16-block: stored group 4t..4t+3 = original {2t,2t+1,2t+8,2t+9},
// so one 8-byte load = one (b0,b1) fragment register pair.
// S = qh*kh + ql*kh : Q is exact (hi+lo), K fp16-rounded (error ~2e-3 logit,
// same magnitude as the f16-acc noise previous passing kernels carried).
// ---------------------------------------------------------------------------
__device__ __half g_Qhi[3 * 2 * NTOK * CDIM];   // [br][b][n][c'] * log2e, hi
__device__ __half g_Qlo[3 * 2 * NTOK * CDIM];   // residual lo
__device__ __half g_KThi[3 * 2 * NTOK * CDIM];  // [ks][b][j][c'] fp16
__device__ __half g_Vh [3 * 2 * CDIM * NTOK];   // [br][b][c][j']

__device__ __host__ __forceinline__ int perm16(int c) {
    int t = (c & 7) >> 1;
    return 4 * t + ((c >> 3) & 1) * 2 + (c & 1);
}

// ---------------------------------------------------------------------------
// Preprocessing
// ---------------------------------------------------------------------------
__global__ void prep_q(const float* __restrict__ q0, const float* __restrict__ q1,
                       const float* __restrict__ q2) {
    int z = blockIdx.y;
    const float* src = (z == 0) ? q0 : (z == 1) ? q1 : q2;
    int i = blockIdx.x * blockDim.x + threadIdx.x;     // [0, 524288)
    float v = src[i] * L2E;
    __half h = __float2half_rn(v);
    int c = i & 63, n = i >> 6;
    int pc = (c & 48) | perm16(c & 15);
    size_t o = (size_t)z * 2 * NTOK * CDIM + (size_t)n * 64 + pc;
    g_Qhi[o] = h;
    g_Qlo[o] = __float2half_rn(v - __half2float(h));
}

__global__ void prep_v(const float* __restrict__ v0, const float* __restrict__ v1,
                       const float* __restrict__ v2) {
    int z = blockIdx.y;
    const float* src = (z == 0) ? v0 : (z == 1) ? v1 : v2;
    int i = blockIdx.x * blockDim.x + threadIdx.x;
    int j = i & 4095, c = i >> 12;
    int pj = (j & ~15) | perm16(j & 15);
    g_Vh[(size_t)z * 2 * CDIM * NTOK + (size_t)c * NTOK + pj] = __float2half_rn(src[i]);
}

// k [b][c][j] -> kT [j][c'] fp16 (perm16 on c). 32x32 tiles, block (32,8).
__global__ void prep_k(const float* __restrict__ k0, const float* __restrict__ k1,
                       const float* __restrict__ k2) {
    __shared__ float tile[32][33];
    int zb = blockIdx.z;
    int ks = zb >> 1, b = zb & 1;
    const float* src = ((ks == 0) ? k0 : (ks == 1) ? k1 : k2) + (size_t)b * CDIM * NTOK;
    int j0 = blockIdx.x * 32, c0 = blockIdx.y * 32;
    int tx = threadIdx.x, ty = threadIdx.y;
#pragma unroll
    for (int yy = 0; yy < 32; yy += 8)
        tile[ty + yy][tx] = src[(size_t)(c0 + ty + yy) * NTOK + j0 + tx];
    __syncthreads();
    size_t dstbase = ((size_t)ks * 2 + b) * NTOK * CDIM;
    int c = c0 + tx;
    int pc = (c & 48) | perm16(c & 15);
#pragma unroll
    for (int yy = 0; yy < 32; yy += 8) {
        int jl = ty + yy;
        g_KThi[dstbase + (size_t)(j0 + jl) * CDIM + pc] = __float2half_rn(tile[tx][jl]);
    }
}

// ---------------------------------------------------------------------------
// Fast exp2 (FMA pipe). x <= 0 expected; clamped.
// ---------------------------------------------------------------------------
__device__ __forceinline__ float exp2_fast(float x) {
    x = fmaxf(x, -120.0f);
    float r  = __fadd_rn(x, 12582912.0f);
    float k  = __fadd_rn(r, -12582912.0f);
    int   ik = __float_as_int(r) - 0x4B400000;
    float f  = x - k;                              // [-0.5, 0.5]
    float p  = 9.618129107e-3f;
    p = fmaf(p, f, 5.550410866e-2f);
    p = fmaf(p, f, 2.402265069e-1f);
    p = fmaf(p, f, 6.931471806e-1f);
    p = fmaf(p, f, 1.0f);
    return __int_as_float(__float_as_int(p) + (ik << 23));
}

__device__ __forceinline__ uint32_t pack_h2(float a, float b) {
    __half2 h = __floats2half2_rn(a, b);
    return *reinterpret_cast<uint32_t*>(&h);
}
__device__ __forceinline__ void cp_async16(uint32_t saddr, const void* g) {
    asm volatile("cp.async.cg.shared.global [%0], [%1], 16;" :: "r"(saddr), "l"(g));
}

#define MMA16816(D, A, B0, B1)                                                        \
    asm volatile("mma.sync.aligned.m16n8k16.row.col.f32.f16.f16.f32 "                 \
                 "{%0,%1,%2,%3},{%4,%5,%6,%7},{%8,%9},{%0,%1,%2,%3};"                 \
                 : "+f"((D)[0]), "+f"((D)[1]), "+f"((D)[2]), "+f"((D)[3])             \
                 : "r"((A)[0]), "r"((A)[1]), "r"((A)[2]), "r"((A)[3]),                \
                   "r"(B0), "r"(B1))

// ---------------------------------------------------------------------------
// Flash attention + fused conv epilogue.
// grid (32 q-tiles, 18 problems), 256 thr (8 warps x 16 q-rows), 2 CTAs/SM.
// GEMM1 = 2 f32-acc MMAs per fragment (qh*kh + ql*kh).
// Smem per stage: K 64x80 halves (10240B) + V 64x80 (10240B); 3 stages.
// ---------------------------------------------------------------------------
#define KROWH 80                    // K row stride (halves); conflict-free LDS.64
#define VROWH 80                    // V row stride (halves)
#define KTILE_H (64 * KROWH)        // 5120
#define VTILE_H (64 * VROWH)        // 5120
#define BUF_H  (KTILE_H + VTILE_H)  // 10240 halves per stage
#define SMEM_FLASH (3 * BUF_H * 2)  // 61440 bytes

__global__ void __launch_bounds__(256, 2) flash_kernel(
    const float* __restrict__ w0, const float* __restrict__ w1, const float* __restrict__ w2,
    const float* __restrict__ bi0, const float* __restrict__ bi1, const float* __restrict__ bi2,
    const float* __restrict__ x0, const float* __restrict__ x1, const float* __restrict__ x2,
    float* __restrict__ out)
{
    extern __shared__ __half sm[];
    const int tid = threadIdx.x;
    const int wi = tid >> 5, lane = tid & 31;
    const int g = lane >> 2, t = lane & 3;
    const int pidx = blockIdx.y;
    const int br = pidx / 6, rem = pidx % 6;
    const int ks = rem >> 1, b = rem & 1;
    const int i0 = blockIdx.x * BM + wi * 16;
    const int hswap = wi & 1;          // phase stagger across warps

    const size_t qoff = ((size_t)(br * 2 + b)) * NTOK * CDIM;
    const size_t koff = ((size_t)(ks * 2 + b)) * NTOK * CDIM;
    const size_t voff = ((size_t)(br * 2 + b)) * CDIM * NTOK;

    const uint32_t smbase = (uint32_t)__cvta_generic_to_shared(sm);

    // Q fragments (persist)
    uint32_t qh[4][4], ql[4][4];
    {
        const __half* Qh = g_Qhi + qoff;
        const __half* Ql = g_Qlo + qoff;
#pragma unroll
        for (int kc = 0; kc < 4; kc++) {
            int co = kc * 16 + 4 * t;
            uint2 u;
            u = *reinterpret_cast<const uint2*>(Qh + (size_t)(i0 + g) * 64 + co);
            qh[kc][0] = u.x; qh[kc][2] = u.y;
            u = *reinterpret_cast<const uint2*>(Qh + (size_t)(i0 + g + 8) * 64 + co);
            qh[kc][1] = u.x; qh[kc][3] = u.y;
            u = *reinterpret_cast<const uint2*>(Ql + (size_t)(i0 + g) * 64 + co);
            ql[kc][0] = u.x; ql[kc][2] = u.y;
            u = *reinterpret_cast<const uint2*>(Ql + (size_t)(i0 + g + 8) * 64 + co);
            ql[kc][1] = u.x; ql[kc][3] = u.y;
        }
    }

    float m_a = -1e30f, m_b = -1e30f, l_a = 0.0f, l_b = 0.0f;
    float acc[8][4];
#pragma unroll
    for (int n = 0; n < 8; n++)
#pragma unroll
        for (int q = 0; q < 4; q++) acc[n][q] = 0.0f;

    auto issue = [&](int stage, int jt) {
        // K: 64 rows x 64 halves = 512 16B-chunks
#pragma unroll
        for (int r = 0; r < 2; r++) {
            int idx = tid + 256 * r;
            int row = idx >> 3, c8 = idx & 7;
            int soff = stage * BUF_H + row * KROWH + c8 * 8;
            const __half* gp = g_KThi + koff + (size_t)(jt + row) * 64 + c8 * 8;
            cp_async16(smbase + soff * 2, gp);
        }
        // V: 64 rows x 64 halves = 512 chunks
#pragma unroll
        for (int r = 0; r < 2; r++) {
            int idx = tid + 256 * r;
            int row = idx >> 3, c8 = idx & 7;
            int soff = stage * BUF_H + KTILE_H + row * VROWH + c8 * 8;
            const __half* gp = g_Vh + voff + (size_t)row * NTOK + jt + c8 * 8;
            cp_async16(smbase + soff * 2, gp);
        }
    };

    issue(0, 0);
    asm volatile("cp.async.commit_group;");
    issue(1, BN);
    asm volatile("cp.async.commit_group;");

#pragma unroll 1
    for (int it = 0; it < NITER; it++) {
        if (it < NITER - 1) {
            asm volatile("cp.async.wait_group 1;" ::: "memory");
        } else {
            asm volatile("cp.async.wait_group 0;" ::: "memory");
        }
        __syncthreads();
        if (it < NITER - 2) {
            int nx = it + 2;
            issue(nx % 3, nx * BN);
            asm volatile("cp.async.commit_group;");
        }

        const __half* sK = sm + (it % 3) * BUF_H;
        const __half* sV = sK + KTILE_H;

#pragma unroll
        for (int h = 0; h < 2; h++) {
            const int half = h ^ hswap;
            float S[4][4];
#pragma unroll
            for (int n = 0; n < 4; n++)
                S[n][0] = S[n][1] = S[n][2] = S[n][3] = 0.0f;

            // GEMM1: S = qh*kh + ql*kh (both f32 acc)
#pragma unroll
            for (int kc = 0; kc < 4; kc++) {
#pragma unroll
                for (int n2 = 0; n2 < 4; n2++) {
                    int nc = 4 * half + n2;
                    const __half* kp = sK + (8 * nc + g) * KROWH + kc * 16 + 4 * t;
                    uint2 kb = *reinterpret_cast<const uint2*>(kp);
                    MMA16816(S[n2], qh[kc], kb.x, kb.y);
                    MMA16816(S[n2], ql[kc], kb.x, kb.y);
                }
            }

            // Online softmax over 32 cols (base 2)
            float rmax_a = fmaxf(fmaxf(S[0][0], S[0][1]), fmaxf(S[1][0], S[1][1]));
            float rmax_b = fmaxf(fmaxf(S[0][2], S[0][3]), fmaxf(S[1][2], S[1][3]));
            rmax_a = fmaxf(rmax_a, fmaxf(fmaxf(S[2][0], S[2][1]), fmaxf(S[3][0], S[3][1])));
            rmax_b = fmaxf(rmax_b, fmaxf(fmaxf(S[2][2], S[2][3]), fmaxf(S[3][2], S[3][3])));
            rmax_a = fmaxf(rmax_a, __shfl_xor_sync(0xffffffffu, rmax_a, 1));
            rmax_a = fmaxf(rmax_a, __shfl_xor_sync(0xffffffffu, rmax_a, 2));
            rmax_b = fmaxf(rmax_b, __shfl_xor_sync(0xffffffffu, rmax_b, 1));
            rmax_b = fmaxf(rmax_b, __shfl_xor_sync(0xffffffffu, rmax_b, 2));

            float mna = fmaxf(m_a, rmax_a), mnb = fmaxf(m_b, rmax_b);
            if (!__all_sync(0xffffffffu, (mna == m_a) & (mnb == m_b))) {
                float sca = exp2_fast(m_a - mna), scb = exp2_fast(m_b - mnb);
                m_a = mna; m_b = mnb;
                l_a *= sca; l_b *= scb;
#pragma unroll
                for (int nc = 0; nc < 8; nc++) {
                    acc[nc][0] *= sca; acc[nc][1] *= sca;
                    acc[nc][2] *= scb; acc[nc][3] *= scb;
                }
            }
#pragma unroll
            for (int n2 = 0; n2 < 4; n2++) {
                S[n2][0] = exp2_fast(S[n2][0] - m_a);
                S[n2][1] = exp2_fast(S[n2][1] - m_a);
                S[n2][2] = exp2_fast(S[n2][2] - m_b);
                S[n2][3] = exp2_fast(S[n2][3] - m_b);
                l_a += S[n2][0] + S[n2][1];
                l_b += S[n2][2] + S[n2][3];
            }

            // GEMM2: acc += P * V^T
#pragma unroll
            for (int kj2 = 0; kj2 < 2; kj2++) {
                int kj = 2 * half + kj2;
                uint32_t pa[4];
                pa[0] = pack_h2(S[2 * kj2][0],     S[2 * kj2][1]);
                pa[1] = pack_h2(S[2 * kj2][2],     S[2 * kj2][3]);
                pa[2] = pack_h2(S[2 * kj2 + 1][0], S[2 * kj2 + 1][1]);
                pa[3] = pack_h2(S[2 * kj2 + 1][2], S[2 * kj2 + 1][3]);
#pragma unroll
                for (int nc = 0; nc < 8; nc++) {
                    const __half* vp = sV + (8 * nc + g) * VROWH + kj * 16 + 4 * t;
                    uint2 vv = *reinterpret_cast<const uint2*>(vp);
                    MMA16816(acc[nc], pa, vv.x, vv.y);
                }
            }
        }
    }

    // Row denominators: sum partials across the 4 t-lanes of each group
    l_a += __shfl_xor_sync(0xffffffffu, l_a, 1);
    l_a += __shfl_xor_sync(0xffffffffu, l_a, 2);
    l_b += __shfl_xor_sync(0xffffffffu, l_b, 1);
    l_b += __shfl_xor_sync(0xffffffffu, l_b, 2);
    float ia = 1.0f / l_a, ib = 1.0f / l_b;

    // ---------------- Fused conv epilogue ----------------
    const float* w  = (br == 0) ? w0  : (br == 1) ? w1  : w2;
    const float* bi = (br == 0) ? bi0 : (br == 1) ? bi1 : bi2;
    const float* x  = (br == 0) ? x0  : (br == 1) ? x1  : x2;

    __syncthreads();   // all reads of pipeline smem done; reuse stage 0
    __half* ws = sm;                       // [64][80] halves, c permuted
    float*  bsf = (float*)(sm + 64 * VROWH);
#pragma unroll
    for (int r = 0; r < 16; r++) {
        int idx = tid + 256 * r;           // 4096 weights
        int oc = idx >> 6, c = idx & 63;
        ws[oc * VROWH + (c & 48) + perm16(c & 15)] = __float2half_rn(w[idx]);
    }
    if (tid < 64) bsf[tid] = bi[tid];
    __syncthreads();

    // A fragments = normalized O (same repacking pattern as P)
    uint32_t oa[4][4];
#pragma unroll
    for (int kc = 0; kc < 4; kc++) {
        oa[kc][0] = pack_h2(acc[2 * kc][0] * ia,     acc[2 * kc][1] * ia);
        oa[kc][1] = pack_h2(acc[2 * kc][2] * ib,     acc[2 * kc][3] * ib);
        oa[kc][2] = pack_h2(acc[2 * kc + 1][0] * ia, acc[2 * kc + 1][1] * ia);
        oa[kc][3] = pack_h2(acc[2 * kc + 1][2] * ib, acc[2 * kc + 1][3] * ib);
    }

    float D[8][4];
#pragma unroll
    for (int n = 0; n < 8; n++) D[n][0] = D[n][1] = D[n][2] = D[n][3] = 0.0f;
#pragma unroll
    for (int kc = 0; kc < 4; kc++) {
#pragma unroll
        for (int nw = 0; nw < 8; nw++) {
            const __half* wp = ws + (8 * nw + g) * VROWH + kc * 16 + 4 * t;
            uint2 wb = *reinterpret_cast<const uint2*>(wp);
            MMA16816(D[nw], oa[kc], wb.x, wb.y);
        }
    }

    // out[br][b][ks*64+oc][i] = D + bias[oc] + x[b][oc][i]
    float* ob = out + (size_t)br * (2 * 192 * NTOK) + (size_t)b * (192 * NTOK)
                    + (size_t)ks * (64 * NTOK);
    const float* xb = x + (size_t)b * CDIM * NTOK;
#pragma unroll
    for (int nw = 0; nw < 8; nw++) {
        int oc = 8 * nw + 2 * t;
        float bs0 = bsf[oc], bs1 = bsf[oc + 1];
        size_t o00 = (size_t)oc * NTOK + i0 + g;
        ob[o00]            = D[nw][0] + bs0 + xb[o00];
        ob[o00 + NTOK]     = D[nw][1] + bs1 + xb[o00 + NTOK];
        size_t o10 = o00 + 8;
        ob[o10]            = D[nw][2] + bs0 + xb[o10];
        ob[o10 + NTOK]     = D[nw][3] + bs1 + xb[o10 + NTOK];
    }
}

// ---------------------------------------------------------------------------
// Launch. Inputs in setup_inputs() dict-insertion order.
// ---------------------------------------------------------------------------
extern "C" void kernel_launch(void* const* d_in, const int* in_sizes, int n_in,
                              void* d_out, int out_size) {
    const float* poi_q   = (const float*)d_in[0];
    const float* poi_k   = (const float*)d_in[1];
    const float* poi_v   = (const float*)d_in[2];
    const float* x_poi   = (const float*)d_in[3];
    const float* point_q = (const float*)d_in[4];
    const float* point_k = (const float*)d_in[5];
    const float* point_v = (const float*)d_in[6];
    const float* x_point = (const float*)d_in[7];
    const float* pop_q   = (const float*)d_in[8];
    const float* pop_k   = (const float*)d_in[9];
    const float* pop_v   = (const float*)d_in[10];
    const float* x_pop   = (const float*)d_in[11];
    const float* w_poi   = (const float*)d_in[12];
    const float* b_poi   = (const float*)d_in[13];
    const float* w_point = (const float*)d_in[14];
    const float* b_point = (const float*)d_in[15];
    const float* w_pop   = (const float*)d_in[16];
    const float* b_pop   = (const float*)d_in[17];
    float* out = (float*)d_out;

    cudaFuncSetAttribute(flash_kernel, cudaFuncAttributeMaxDynamicSharedMemorySize,
                         SMEM_FLASH);

    prep_q<<<dim3(2048, 3), 256>>>(poi_q, point_q, pop_q);
    prep_v<<<dim3(2048, 3), 256>>>(poi_v, point_v, pop_v);
    prep_k<<<dim3(128, 2, 6), dim3(32, 8)>>>(poi_k, point_k, pop_k);
    flash_kernel<<<dim3(32, 18), 256, SMEM_FLASH>>>(
        w_poi, w_point, w_pop, b_poi, b_point, b_pop,
        x_poi, x_point, x_pop, out);
}

// round 17
// speedup vs baseline: 1.5639x; 1.2257x over previous
#include <cuda_runtime.h>
#include <cuda_fp16.h>
#include <stdint.h>

#define NTOK 4096
#define CDIM 64
#define BM   128
#define BN   64
#define NITER (NTOK / BN)       // 64
#define NPROB 18
#define L2E  1.4426950408889634f

// ---------------------------------------------------------------------------
// Device scratch. Contraction-dim storage uses the MMA-fragment permutation
// within each 16-block: stored group 4t..4t+3 = original {2t,2t+1,2t+8,2t+9},
// so one 8-byte load = one (b0,b1) fragment register pair.
// S = qh*kh, both fp16-rounded (f32 acc). Measured error components:
// K-only rounding gave rel_err 3.49e-4 (R16); Q adds ~3.2e-4 in quadrature.
// ---------------------------------------------------------------------------
__device__ __half g_Qh [3 * 2 * NTOK * CDIM];   // [br][b][n][c'] * log2e
__device__ __half g_KTh[3 * 2 * NTOK * CDIM];   // [ks][b][j][c']
__device__ __half g_Vh [3 * 2 * CDIM * NTOK];   // [br][b][c][j']

__device__ __host__ __forceinline__ int perm16(int c) {
    int t = (c & 7) >> 1;
    return 4 * t + ((c >> 3) & 1) * 2 + (c & 1);
}

// ---------------------------------------------------------------------------
// Preprocessing
// ---------------------------------------------------------------------------
__global__ void prep_q(const float* __restrict__ q0, const float* __restrict__ q1,
                       const float* __restrict__ q2) {
    int z = blockIdx.y;
    const float* src = (z == 0) ? q0 : (z == 1) ? q1 : q2;
    int i = blockIdx.x * blockDim.x + threadIdx.x;     // [0, 524288)
    float v = src[i] * L2E;
    int c = i & 63, n = i >> 6;
    int pc = (c & 48) | perm16(c & 15);
    g_Qh[(size_t)z * 2 * NTOK * CDIM + (size_t)n * 64 + pc] = __float2half_rn(v);
}

__global__ void prep_v(const float* __restrict__ v0, const float* __restrict__ v1,
                       const float* __restrict__ v2) {
    int z = blockIdx.y;
    const float* src = (z == 0) ? v0 : (z == 1) ? v1 : v2;
    int i = blockIdx.x * blockDim.x + threadIdx.x;
    int j = i & 4095, c = i >> 12;
    int pj = (j & ~15) | perm16(j & 15);
    g_Vh[(size_t)z * 2 * CDIM * NTOK + (size_t)c * NTOK + pj] = __float2half_rn(src[i]);
}

// k [b][c][j] -> kT [j][c'] fp16 (perm16 on c). 32x32 tiles, block (32,8).
__global__ void prep_k(const float* __restrict__ k0, const float* __restrict__ k1,
                       const float* __restrict__ k2) {
    __shared__ float tile[32][33];
    int zb = blockIdx.z;
    int ks = zb >> 1, b = zb & 1;
    const float* src = ((ks == 0) ? k0 : (ks == 1) ? k1 : k2) + (size_t)b * CDIM * NTOK;
    int j0 = blockIdx.x * 32, c0 = blockIdx.y * 32;
    int tx = threadIdx.x, ty = threadIdx.y;
#pragma unroll
    for (int yy = 0; yy < 32; yy += 8)
        tile[ty + yy][tx] = src[(size_t)(c0 + ty + yy) * NTOK + j0 + tx];
    __syncthreads();
    size_t dstbase = ((size_t)ks * 2 + b) * NTOK * CDIM;
    int c = c0 + tx;
    int pc = (c & 48) | perm16(c & 15);
#pragma unroll
    for (int yy = 0; yy < 32; yy += 8) {
        int jl = ty + yy;
        g_KTh[dstbase + (size_t)(j0 + jl) * CDIM + pc] = __float2half_rn(tile[tx][jl]);
    }
}

// ---------------------------------------------------------------------------
// Fast exp2 (FMA pipe). x <= 0 expected; clamped.
// ---------------------------------------------------------------------------
__device__ __forceinline__ float exp2_fast(float x) {
    x = fmaxf(x, -120.0f);
    float r  = __fadd_rn(x, 12582912.0f);
    float k  = __fadd_rn(r, -12582912.0f);
    int   ik = __float_as_int(r) - 0x4B400000;
    float f  = x - k;                              // [-0.5, 0.5]
    float p  = 9.618129107e-3f;
    p = fmaf(p, f, 5.550410866e-2f);
    p = fmaf(p, f, 2.402265069e-1f);
    p = fmaf(p, f, 6.931471806e-1f);
    p = fmaf(p, f, 1.0f);
    return __int_as_float(__float_as_int(p) + (ik << 23));
}

__device__ __forceinline__ uint32_t pack_h2(float a, float b) {
    __half2 h = __floats2half2_rn(a, b);
    return *reinterpret_cast<uint32_t*>(&h);
}
__device__ __forceinline__ void cp_async16(uint32_t saddr, const void* g) {
    asm volatile("cp.async.cg.shared.global [%0], [%1], 16;" :: "r"(saddr), "l"(g));
}

#define MMA16816(D, A, B0, B1)                                                        \
    asm volatile("mma.sync.aligned.m16n8k16.row.col.f32.f16.f16.f32 "                 \
                 "{%0,%1,%2,%3},{%4,%5,%6,%7},{%8,%9},{%0,%1,%2,%3};"                 \
                 : "+f"((D)[0]), "+f"((D)[1]), "+f"((D)[2]), "+f"((D)[3])             \
                 : "r"((A)[0]), "r"((A)[1]), "r"((A)[2]), "r"((A)[3]),                \
                   "r"(B0), "r"(B1))

// ---------------------------------------------------------------------------
// Flash attention + fused conv epilogue.
// grid (32 q-tiles, 18 problems), 256 thr (8 warps x 16 q-rows), 2 CTAs/SM.
// GEMM1 = 1 f32-acc MMA per fragment (plain fp16 QK).
// Smem per stage: K 64x80 halves (10240B) + V 64x80 (10240B); 3 stages.
// ---------------------------------------------------------------------------
#define KROWH 80                    // K row stride (halves); conflict-free LDS.64
#define VROWH 80                    // V row stride (halves)
#define KTILE_H (64 * KROWH)        // 5120
#define VTILE_H (64 * VROWH)        // 5120
#define BUF_H  (KTILE_H + VTILE_H)  // 10240 halves per stage
#define SMEM_FLASH (3 * BUF_H * 2)  // 61440 bytes

__global__ void __launch_bounds__(256, 2) flash_kernel(
    const float* __restrict__ w0, const float* __restrict__ w1, const float* __restrict__ w2,
    const float* __restrict__ bi0, const float* __restrict__ bi1, const float* __restrict__ bi2,
    const float* __restrict__ x0, const float* __restrict__ x1, const float* __restrict__ x2,
    float* __restrict__ out)
{
    extern __shared__ __half sm[];
    const int tid = threadIdx.x;
    const int wi = tid >> 5, lane = tid & 31;
    const int g = lane >> 2, t = lane & 3;
    const int pidx = blockIdx.y;
    const int br = pidx / 6, rem = pidx % 6;
    const int ks = rem >> 1, b = rem & 1;
    const int i0 = blockIdx.x * BM + wi * 16;
    const int hswap = wi & 1;          // phase stagger across warps

    const size_t qoff = ((size_t)(br * 2 + b)) * NTOK * CDIM;
    const size_t koff = ((size_t)(ks * 2 + b)) * NTOK * CDIM;
    const size_t voff = ((size_t)(br * 2 + b)) * CDIM * NTOK;

    const uint32_t smbase = (uint32_t)__cvta_generic_to_shared(sm);

    // Q fragments (persist)
    uint32_t qh[4][4];
    {
        const __half* Qh = g_Qh + qoff;
#pragma unroll
        for (int kc = 0; kc < 4; kc++) {
            int co = kc * 16 + 4 * t;
            uint2 u;
            u = *reinterpret_cast<const uint2*>(Qh + (size_t)(i0 + g) * 64 + co);
            qh[kc][0] = u.x; qh[kc][2] = u.y;
            u = *reinterpret_cast<const uint2*>(Qh + (size_t)(i0 + g + 8) * 64 + co);
            qh[kc][1] = u.x; qh[kc][3] = u.y;
        }
    }

    float m_a = -1e30f, m_b = -1e30f, l_a = 0.0f, l_b = 0.0f;
    float acc[8][4];
#pragma unroll
    for (int n = 0; n < 8; n++)
#pragma unroll
        for (int q = 0; q < 4; q++) acc[n][q] = 0.0f;

    auto issue = [&](int stage, int jt) {
        // K: 64 rows x 64 halves = 512 16B-chunks
#pragma unroll
        for (int r = 0; r < 2; r++) {
            int idx = tid + 256 * r;
            int row = idx >> 3, c8 = idx & 7;
            int soff = stage * BUF_H + row * KROWH + c8 * 8;
            const __half* gp = g_KTh + koff + (size_t)(jt + row) * 64 + c8 * 8;
            cp_async16(smbase + soff * 2, gp);
        }
        // V: 64 rows x 64 halves = 512 chunks
#pragma unroll
        for (int r = 0; r < 2; r++) {
            int idx = tid + 256 * r;
            int row = idx >> 3, c8 = idx & 7;
            int soff = stage * BUF_H + KTILE_H + row * VROWH + c8 * 8;
            const __half* gp = g_Vh + voff + (size_t)row * NTOK + jt + c8 * 8;
            cp_async16(smbase + soff * 2, gp);
        }
    };

    issue(0, 0);
    asm volatile("cp.async.commit_group;");
    issue(1, BN);
    asm volatile("cp.async.commit_group;");

#pragma unroll 1
    for (int it = 0; it < NITER; it++) {
        if (it < NITER - 1) {
            asm volatile("cp.async.wait_group 1;" ::: "memory");
        } else {
            asm volatile("cp.async.wait_group 0;" ::: "memory");
        }
        __syncthreads();
        if (it < NITER - 2) {
            int nx = it + 2;
            issue(nx % 3, nx * BN);
            asm volatile("cp.async.commit_group;");
        }

        const __half* sK = sm + (it % 3) * BUF_H;
        const __half* sV = sK + KTILE_H;

#pragma unroll
        for (int h = 0; h < 2; h++) {
            const int half = h ^ hswap;
            float S[4][4];
#pragma unroll
            for (int n = 0; n < 4; n++)
                S[n][0] = S[n][1] = S[n][2] = S[n][3] = 0.0f;

            // GEMM1: S = q*k (fp16 inputs, f32 acc)
#pragma unroll
            for (int kc = 0; kc < 4; kc++) {
#pragma unroll
                for (int n2 = 0; n2 < 4; n2++) {
                    int nc = 4 * half + n2;
                    const __half* kp = sK + (8 * nc + g) * KROWH + kc * 16 + 4 * t;
                    uint2 kb = *reinterpret_cast<const uint2*>(kp);
                    MMA16816(S[n2], qh[kc], kb.x, kb.y);
                }
            }

            // Online softmax over 32 cols (base 2)
            float rmax_a = fmaxf(fmaxf(S[0][0], S[0][1]), fmaxf(S[1][0], S[1][1]));
            float rmax_b = fmaxf(fmaxf(S[0][2], S[0][3]), fmaxf(S[1][2], S[1][3]));
            rmax_a = fmaxf(rmax_a, fmaxf(fmaxf(S[2][0], S[2][1]), fmaxf(S[3][0], S[3][1])));
            rmax_b = fmaxf(rmax_b, fmaxf(fmaxf(S[2][2], S[2][3]), fmaxf(S[3][2], S[3][3])));
            rmax_a = fmaxf(rmax_a, __shfl_xor_sync(0xffffffffu, rmax_a, 1));
            rmax_a = fmaxf(rmax_a, __shfl_xor_sync(0xffffffffu, rmax_a, 2));
            rmax_b = fmaxf(rmax_b, __shfl_xor_sync(0xffffffffu, rmax_b, 1));
            rmax_b = fmaxf(rmax_b, __shfl_xor_sync(0xffffffffu, rmax_b, 2));

            float mna = fmaxf(m_a, rmax_a), mnb = fmaxf(m_b, rmax_b);
            if (!__all_sync(0xffffffffu, (mna == m_a) & (mnb == m_b))) {
                float sca = exp2_fast(m_a - mna), scb = exp2_fast(m_b - mnb);
                m_a = mna; m_b = mnb;
                l_a *= sca; l_b *= scb;
#pragma unroll
                for (int nc = 0; nc < 8; nc++) {
                    acc[nc][0] *= sca; acc[nc][1] *= sca;
                    acc[nc][2] *= scb; acc[nc][3] *= scb;
                }
            }
#pragma unroll
            for (int n2 = 0; n2 < 4; n2++) {
                S[n2][0] = exp2_fast(S[n2][0] - m_a);
                S[n2][1] = exp2_fast(S[n2][1] - m_a);
                S[n2][2] = exp2_fast(S[n2][2] - m_b);
                S[n2][3] = exp2_fast(S[n2][3] - m_b);
                l_a += S[n2][0] + S[n2][1];
                l_b += S[n2][2] + S[n2][3];
            }

            // GEMM2: acc += P * V^T
#pragma unroll
            for (int kj2 = 0; kj2 < 2; kj2++) {
                int kj = 2 * half + kj2;
                uint32_t pa[4];
                pa[0] = pack_h2(S[2 * kj2][0],     S[2 * kj2][1]);
                pa[1] = pack_h2(S[2 * kj2][2],     S[2 * kj2][3]);
                pa[2] = pack_h2(S[2 * kj2 + 1][0], S[2 * kj2 + 1][1]);
                pa[3] = pack_h2(S[2 * kj2 + 1][2], S[2 * kj2 + 1][3]);
#pragma unroll
                for (int nc = 0; nc < 8; nc++) {
                    const __half* vp = sV + (8 * nc + g) * VROWH + kj * 16 + 4 * t;
                    uint2 vv = *reinterpret_cast<const uint2*>(vp);
                    MMA16816(acc[nc], pa, vv.x, vv.y);
                }
            }
        }
    }

    // Row denominators: sum partials across the 4 t-lanes of each group
    l_a += __shfl_xor_sync(0xffffffffu, l_a, 1);
    l_a += __shfl_xor_sync(0xffffffffu, l_a, 2);
    l_b += __shfl_xor_sync(0xffffffffu, l_b, 1);
    l_b += __shfl_xor_sync(0xffffffffu, l_b, 2);
    float ia = 1.0f / l_a, ib = 1.0f / l_b;

    // ---------------- Fused conv epilogue ----------------
    const float* w  = (br == 0) ? w0  : (br == 1) ? w1  : w2;
    const float* bi = (br == 0) ? bi0 : (br == 1) ? bi1 : bi2;
    const float* x  = (br == 0) ? x0  : (br == 1) ? x1  : x2;

    __syncthreads();   // all reads of pipeline smem done; reuse stage 0
    __half* ws = sm;                       // [64][80] halves, c permuted
    float*  bsf = (float*)(sm + 64 * VROWH);
#pragma unroll
    for (int r = 0; r < 16; r++) {
        int idx = tid + 256 * r;           // 4096 weights
        int oc = idx >> 6, c = idx & 63;
        ws[oc * VROWH + (c & 48) + perm16(c & 15)] = __float2half_rn(w[idx]);
    }
    if (tid < 64) bsf[tid] = bi[tid];
    __syncthreads();

    // A fragments = normalized O (same repacking pattern as P)
    uint32_t oa[4][4];
#pragma unroll
    for (int kc = 0; kc < 4; kc++) {
        oa[kc][0] = pack_h2(acc[2 * kc][0] * ia,     acc[2 * kc][1] * ia);
        oa[kc][1] = pack_h2(acc[2 * kc][2] * ib,     acc[2 * kc][3] * ib);
        oa[kc][2] = pack_h2(acc[2 * kc + 1][0] * ia, acc[2 * kc + 1][1] * ia);
        oa[kc][3] = pack_h2(acc[2 * kc + 1][2] * ib, acc[2 * kc + 1][3] * ib);
    }

    float D[8][4];
#pragma unroll
    for (int n = 0; n < 8; n++) D[n][0] = D[n][1] = D[n][2] = D[n][3] = 0.0f;
#pragma unroll
    for (int kc = 0; kc < 4; kc++) {
#pragma unroll
        for (int nw = 0; nw < 8; nw++) {
            const __half* wp = ws + (8 * nw + g) * VROWH + kc * 16 + 4 * t;
            uint2 wb = *reinterpret_cast<const uint2*>(wp);
            MMA16816(D[nw], oa[kc], wb.x, wb.y);
        }
    }

    // out[br][b][ks*64+oc][i] = D + bias[oc] + x[b][oc][i]
    float* ob = out + (size_t)br * (2 * 192 * NTOK) + (size_t)b * (192 * NTOK)
                    + (size_t)ks * (64 * NTOK);
    const float* xb = x + (size_t)b * CDIM * NTOK;
#pragma unroll
    for (int nw = 0; nw < 8; nw++) {
        int oc = 8 * nw + 2 * t;
        float bs0 = bsf[oc], bs1 = bsf[oc + 1];
        size_t o00 = (size_t)oc * NTOK + i0 + g;
        ob[o00]            = D[nw][0] + bs0 + xb[o00];
        ob[o00 + NTOK]     = D[nw][1] + bs1 + xb[o00 + NTOK];
        size_t o10 = o00 + 8;
        ob[o10]            = D[nw][2] + bs0 + xb[o10];
        ob[o10 + NTOK]     = D[nw][3] + bs1 + xb[o10 + NTOK];
    }
}

// ---------------------------------------------------------------------------
// Launch. Inputs in setup_inputs() dict-insertion order.
// ---------------------------------------------------------------------------
extern "C" void kernel_launch(void* const* d_in, const int* in_sizes, int n_in,
                              void* d_out, int out_size) {
    const float* poi_q   = (const float*)d_in[0];
    const float* poi_k   = (const float*)d_in[1];
    const float* poi_v   = (const float*)d_in[2];
    const float* x_poi   = (const float*)d_in[3];
    const float* point_q = (const float*)d_in[4];
    const float* point_k = (const float*)d_in[5];
    const float* point_v = (const float*)d_in[6];
    const float* x_point = (const float*)d_in[7];
    const float* pop_q   = (const float*)d_in[8];
    const float* pop_k   = (const float*)d_in[9];
    const float* pop_v   = (const float*)d_in[10];
    const float* x_pop   = (const float*)d_in[11];
    const float* w_poi   = (const float*)d_in[12];
    const float* b_poi   = (const float*)d_in[13];
    const float* w_point = (const float*)d_in[14];
    const float* b_point = (const float*)d_in[15];
    const float* w_pop   = (const float*)d_in[16];
    const float* b_pop   = (const float*)d_in[17];
    float* out = (float*)d_out;

    cudaFuncSetAttribute(flash_kernel, cudaFuncAttributeMaxDynamicSharedMemorySize,
                         SMEM_FLASH);

    prep_q<<<dim3(2048, 3), 256>>>(poi_q, point_q, pop_q);
    prep_v<<<dim3(2048, 3), 256>>>(poi_v, point_v, pop_v);
    prep_k<<<dim3(128, 2, 6), dim3(32, 8)>>>(poi_k, point_k, pop_k);
    flash_kernel<<<dim3(32, 18), 256, SMEM_FLASH>>>(
        w_poi, w_point, w_pop, b_poi, b_point, b_pop,
        x_poi, x_point, x_pop, out);
}